// round 9
// baseline (speedup 1.0000x reference)
#include <cuda_runtime.h>
#include <math.h>

// Problem constants: B=32, C=3, H=W=512
#define BB 32
#define CC 3
#define HH 512
#define WW 512
#define PX 4   // pixels per thread, warp-interleaved (stride 32)

// Single fused kernel: per-thread theta recompute (uniform per block, cheap),
// warp-interleaved bilinear gather with channel-batched loads.
__global__ __launch_bounds__(256) void warp_kernel(const float* __restrict__ x,
                                                   const float* __restrict__ thetas,
                                                   const float* __restrict__ l1s,
                                                   const float* __restrict__ l2s,
                                                   float* __restrict__ out) {
    int lane = threadIdx.x;                           // 0..31
    int py   = blockIdx.y * blockDim.y + threadIdx.y;
    int b    = blockIdx.z;
    int px0  = blockIdx.x * (32 * PX) + lane;

    // theta = R(-th)^T diag(1/l1,1/l2) R(-th) with th = -theta (translation is 0)
    float th = -__ldg(thetas + b);
    float c, s;
    __sincosf(th, &s, &c);
    float il1 = 1.0f / __ldg(l1s + b);
    float il2 = 1.0f / __ldg(l2s + b);
    float m00 = c * c * il1 + s * s * il2;
    float m11 = s * s * il1 + c * c * il2;
    float m01 = c * s * (il2 - il1);
    float m10 = m01;

    float X = ((float)px0 + 0.5f) * (2.0f / (float)WW) - 1.0f;
    float Y = ((float)py + 0.5f) * (2.0f / (float)HH) - 1.0f;

    float gx = (m00 * X + m01 * Y + 1.0f) * ((float)WW * 0.5f) - 0.5f;
    float gy = (m10 * X + m11 * Y + 1.0f) * ((float)HH * 0.5f) - 0.5f;
    float sx = 32.0f * m00;
    float sy = 32.0f * m10;

    const float* p0 = x + (size_t)b * CC * HH * WW;
    const float* p1 = p0 + HH * WW;
    const float* p2 = p1 + HH * WW;
    float* ob = out + ((size_t)b * CC) * HH * WW + (size_t)py * WW + px0;

    float v0[PX], v1[PX], v2[PX];

#pragma unroll
    for (int k = 0; k < PX; k++) {
        float x0f = floorf(gx);
        float y0f = floorf(gy);
        int x0 = (int)x0f;
        int y0 = (int)y0f;

        float wx1 = gx - x0f;
        float wx0 = 1.0f - wx1;
        float wy1 = gy - y0f;
        float wy0 = 1.0f - wy1;

        // fold border masks into the 1D weights
        float cx0 = ((unsigned)x0       < (unsigned)WW) ? wx0 : 0.0f;
        float cx1 = ((unsigned)(x0 + 1) < (unsigned)WW) ? wx1 : 0.0f;
        float cy0 = ((unsigned)y0       < (unsigned)HH) ? wy0 : 0.0f;
        float cy1 = ((unsigned)(y0 + 1) < (unsigned)HH) ? wy1 : 0.0f;

        float w00 = cy0 * cx0;
        float w01 = cy0 * cx1;
        float w10 = cy1 * cx0;
        float w11 = cy1 * cx1;

        int i0 = y0 * WW + x0;  // raw index; loads are weight-guarded

        // 12 independent guarded loads (3 channels x 4 corners) — front-batched
        float a0 = 0.f, b0q = 0.f, c0q = 0.f, d0q = 0.f;
        float a1 = 0.f, b1q = 0.f, c1q = 0.f, d1q = 0.f;
        float a2 = 0.f, b2q = 0.f, c2q = 0.f, d2q = 0.f;
        if (w00 != 0.0f) {
            a0 = __ldg(p0 + i0);
            a1 = __ldg(p1 + i0);
            a2 = __ldg(p2 + i0);
        }
        if (w01 != 0.0f) {
            b0q = __ldg(p0 + i0 + 1);
            b1q = __ldg(p1 + i0 + 1);
            b2q = __ldg(p2 + i0 + 1);
        }
        if (w10 != 0.0f) {
            c0q = __ldg(p0 + i0 + WW);
            c1q = __ldg(p1 + i0 + WW);
            c2q = __ldg(p2 + i0 + WW);
        }
        if (w11 != 0.0f) {
            d0q = __ldg(p0 + i0 + WW + 1);
            d1q = __ldg(p1 + i0 + WW + 1);
            d2q = __ldg(p2 + i0 + WW + 1);
        }

        v0[k] = w00 * a0 + w01 * b0q + w10 * c0q + w11 * d0q;
        v1[k] = w00 * a1 + w01 * b1q + w10 * c1q + w11 * d1q;
        v2[k] = w00 * a2 + w01 * b2q + w10 * c2q + w11 * d2q;

        gx += sx;
        gy += sy;
    }

#pragma unroll
    for (int k = 0; k < PX; k++) ob[32 * k]                = v0[k];
#pragma unroll
    for (int k = 0; k < PX; k++) ob[32 * k + HH * WW]      = v1[k];
#pragma unroll
    for (int k = 0; k < PX; k++) ob[32 * k + 2 * HH * WW]  = v2[k];
}

extern "C" void kernel_launch(void* const* d_in, const int* in_sizes, int n_in,
                              void* d_out, int out_size) {
    const float* x      = (const float*)d_in[0];
    const float* thetas = (const float*)d_in[1];
    const float* l1s    = (const float*)d_in[2];
    const float* l2s    = (const float*)d_in[3];
    float* out = (float*)d_out;

    dim3 block(32, 8, 1);
    dim3 grid(WW / (32 * PX), HH / 8, BB);   // 4 x 64 x 32 = 8192 CTAs
    warp_kernel<<<grid, block>>>(x, thetas, l1s, l2s, out);
}